// round 5
// baseline (speedup 1.0000x reference)
#include <cuda_runtime.h>

#define N_NODES 100000
#define N_EDGES 1600000
#define HID 128

typedef unsigned long long u64;

// Scratch (__device__ globals per allocation rules)
__device__ float4 g_x4[N_NODES];    // (x0, x1, x2, 1.0)
__device__ float4 g_agg4[N_NODES];  // (sum x0, sum x1, sum x2, deg)
__device__ float4 g_w1[HID];        // (B0,B1,B2,C): B = W_lift@W_rel, C = b_lift@W_rel
__device__ float4 g_w2[HID];        // (A0,A1,A2,D): A = W_lift@W_root, D = b_lift@W_root + b_rel
__device__ float  g_wp[HID];        // W_proj

__device__ __forceinline__ u64 pk(float lo, float hi) {
    u64 r; asm("mov.b64 %0, {%1, %2};" : "=l"(r) : "f"(lo), "f"(hi)); return r;
}
__device__ __forceinline__ u64 pk1(float v) { return pk(v, v); }
#define FMA2(d, a, b, c) asm("fma.rn.f32x2 %0, %1, %2, %3;" : "=l"(d) : "l"(a), "l"(b), "l"(c))
#define UNPK(lo, hi, v)  asm("mov.b64 {%0, %1}, %2;" : "=f"(lo), "=f"(hi) : "l"(v))

// ---------------------------------------------------------------------------
// Kernel 1 (1024 threads/block):
//   block 0   : weight folding, k split 8 ways (16 serial k's) + smem reduce
//   blocks 1..: pack x into (x,1) float4 + zero agg
// ---------------------------------------------------------------------------
__global__ void __launch_bounds__(1024)
prep_pack_kernel(const float* __restrict__ x,
                 const float* __restrict__ W_lift,
                 const float* __restrict__ b_lift,
                 const float* __restrict__ W_rel,
                 const float* __restrict__ b_rel,
                 const float* __restrict__ W_root,
                 const float* __restrict__ W_proj) {
    if (blockIdx.x == 0) {
        __shared__ float red[8][8][HID];  // [kgroup][chain][f] = 32KB
        int f = threadIdx.x & 127;
        int g = threadIdx.x >> 7;  // 0..7, each sums 16 k's
        float b0 = 0.f, b1 = 0.f, b2 = 0.f, c = 0.f;
        float a0 = 0.f, a1 = 0.f, a2 = 0.f, d = 0.f;
        int k0 = g * 16;
#pragma unroll
        for (int i = 0; i < 16; i++) {
            int k = k0 + i;
            float wr = W_rel[k * HID + f];
            float wo = W_root[k * HID + f];
            float l0 = W_lift[0 * HID + k];
            float l1 = W_lift[1 * HID + k];
            float l2 = W_lift[2 * HID + k];
            float bl = b_lift[k];
            b0 += l0 * wr; b1 += l1 * wr; b2 += l2 * wr; c += bl * wr;
            a0 += l0 * wo; a1 += l1 * wo; a2 += l2 * wo; d += bl * wo;
        }
        red[g][0][f] = b0; red[g][1][f] = b1; red[g][2][f] = b2; red[g][3][f] = c;
        red[g][4][f] = a0; red[g][5][f] = a1; red[g][6][f] = a2; red[g][7][f] = d;
        __syncthreads();
        if (g == 0) {
            float s[8];
#pragma unroll
            for (int ch = 0; ch < 8; ch++) {
                float v = red[0][ch][f];
#pragma unroll
                for (int gg = 1; gg < 8; gg++) v += red[gg][ch][f];
                s[ch] = v;
            }
            g_w1[f] = make_float4(s[0], s[1], s[2], s[3]);
            g_w2[f] = make_float4(s[4], s[5], s[6], s[7] + b_rel[f]);
            g_wp[f] = W_proj[f];
        }
    } else {
        int n = (blockIdx.x - 1) * 1024 + threadIdx.x;
        if (n < N_NODES) {
            g_x4[n] = make_float4(x[3 * n], x[3 * n + 1], x[3 * n + 2], 1.0f);
            g_agg4[n] = make_float4(0.f, 0.f, 0.f, 0.f);
        }
    }
}

// ---------------------------------------------------------------------------
// Kernel 2: scatter-add of (x,1) — 4 edges per thread, int4 index loads
// ---------------------------------------------------------------------------
__global__ void scatter_kernel(const int* __restrict__ ei) {
    int t = blockIdx.x * blockDim.x + threadIdx.x;
    int e0 = t * 4;
    if (e0 >= N_EDGES) return;
    int4 s4 = *(const int4*)(ei + e0);            // 4 src (16B aligned)
    int4 d4 = *(const int4*)(ei + N_EDGES + e0);  // 4 dst

    unsigned int s[4] = {(unsigned)s4.x, (unsigned)s4.y, (unsigned)s4.z, (unsigned)s4.w};
    unsigned int q[4] = {(unsigned)d4.x, (unsigned)d4.y, (unsigned)d4.z, (unsigned)d4.w};

    float4 v[4];
    bool ok[4];
#pragma unroll
    for (int i = 0; i < 4; i++) {
        ok[i] = (s[i] < N_NODES) & (q[i] < N_NODES);
        if (ok[i]) v[i] = g_x4[s[i]];   // 4 independent 16B gathers in flight
    }
#pragma unroll
    for (int i = 0; i < 4; i++) {
        if (ok[i]) {
            float* ap = (float*)&g_agg4[q[i]];
            asm volatile("red.global.add.v4.f32 [%0], {%1,%2,%3,%4};"
                         :: "l"(ap), "f"(v[i].x), "f"(v[i].y), "f"(v[i].z), "f"(v[i].w)
                         : "memory");
        }
    }
}

// ---------------------------------------------------------------------------
// Kernel 3: out[n] = sum_f tanh(dot(agg4,w1_f)+dot(x4,w2_f)) * wp_f + b_proj
// f32x2 packed math over feature pairs; 2 nodes per thread.
// ---------------------------------------------------------------------------
__global__ void __launch_bounds__(256)
final_kernel(const float* __restrict__ b_proj, float* __restrict__ out) {
    __shared__ u64 sB0[64], sB1[64], sB2[64], sC[64];
    __shared__ u64 sA0[64], sA1[64], sA2[64], sD[64], sWP[64];
    if (threadIdx.x < 64) {
        int p = threadIdx.x;
        float4 u0 = g_w1[2 * p], u1 = g_w1[2 * p + 1];
        sB0[p] = pk(u0.x, u1.x); sB1[p] = pk(u0.y, u1.y);
        sB2[p] = pk(u0.z, u1.z); sC[p]  = pk(u0.w, u1.w);
        float4 v0 = g_w2[2 * p], v1 = g_w2[2 * p + 1];
        sA0[p] = pk(v0.x, v1.x); sA1[p] = pk(v0.y, v1.y);
        sA2[p] = pk(v0.z, v1.z); sD[p]  = pk(v0.w, v1.w);
        sWP[p] = pk(g_wp[2 * p], g_wp[2 * p + 1]);
    }
    __syncthreads();

    int n0 = (blockIdx.x * blockDim.x + threadIdx.x) * 2;
    if (n0 >= N_NODES) return;  // N_NODES even -> n0+1 always valid here

    float4 aA = g_agg4[n0], aB = g_agg4[n0 + 1];
    float4 xA = g_x4[n0],  xB = g_x4[n0 + 1];

    u64 axA = pk1(aA.x), ayA = pk1(aA.y), azA = pk1(aA.z), awA = pk1(aA.w);
    u64 xxA = pk1(xA.x), xyA = pk1(xA.y), xzA = pk1(xA.z);
    u64 axB = pk1(aB.x), ayB = pk1(aB.y), azB = pk1(aB.z), awB = pk1(aB.w);
    u64 xxB = pk1(xB.x), xyB = pk1(xB.y), xzB = pk1(xB.z);

    u64 accA = pk(0.f, 0.f), accB = pk(0.f, 0.f);

#pragma unroll 8
    for (int p = 0; p < 64; p++) {
        u64 B0 = sB0[p], B1 = sB1[p], B2 = sB2[p], C = sC[p];
        u64 A0 = sA0[p], A1 = sA1[p], A2 = sA2[p], D = sD[p];
        u64 WP = sWP[p];

        u64 pA = D, pB = D;
        FMA2(pA, axA, B0, pA); FMA2(pB, axB, B0, pB);
        FMA2(pA, ayA, B1, pA); FMA2(pB, ayB, B1, pB);
        FMA2(pA, azA, B2, pA); FMA2(pB, azB, B2, pB);
        FMA2(pA, awA, C,  pA); FMA2(pB, awB, C,  pB);
        FMA2(pA, xxA, A0, pA); FMA2(pB, xxB, A0, pB);
        FMA2(pA, xyA, A1, pA); FMA2(pB, xyB, A1, pB);
        FMA2(pA, xzA, A2, pA); FMA2(pB, xzB, A2, pB);

        float a0, a1, b0, b1;
        UNPK(a0, a1, pA); UNPK(b0, b1, pB);
        float t0, t1, t2, t3;
        asm("tanh.approx.f32 %0, %1;" : "=f"(t0) : "f"(a0));
        asm("tanh.approx.f32 %0, %1;" : "=f"(t1) : "f"(a1));
        asm("tanh.approx.f32 %0, %1;" : "=f"(t2) : "f"(b0));
        asm("tanh.approx.f32 %0, %1;" : "=f"(t3) : "f"(b1));
        u64 tA = pk(t0, t1), tB = pk(t2, t3);
        FMA2(accA, tA, WP, accA);
        FMA2(accB, tB, WP, accB);
    }

    float rA0, rA1, rB0, rB1;
    UNPK(rA0, rA1, accA); UNPK(rB0, rB1, accB);
    float bp = b_proj[0];
    out[n0]     = rA0 + rA1 + bp;
    out[n0 + 1] = rB0 + rB1 + bp;
}

// ---------------------------------------------------------------------------
// Launch — inputs: 0:x 1:edge_index(int32) 2:W_lift 3:b_lift 4:W_rel 5:b_rel
//                  6:W_root 7:W_proj 8:b_proj
// ---------------------------------------------------------------------------
extern "C" void kernel_launch(void* const* d_in, const int* in_sizes, int n_in,
                              void* d_out, int out_size) {
    const float* x      = (const float*)d_in[0];
    const int*   ei     = (const int*)d_in[1];
    const float* W_lift = (const float*)d_in[2];
    const float* b_lift = (const float*)d_in[3];
    const float* W_rel  = (const float*)d_in[4];
    const float* b_rel  = (const float*)d_in[5];
    const float* W_root = (const float*)d_in[6];
    const float* W_proj = (const float*)d_in[7];
    const float* b_proj = (const float*)d_in[8];
    float* out = (float*)d_out;

    prep_pack_kernel<<<1 + (N_NODES + 1023) / 1024, 1024>>>(
        x, W_lift, b_lift, W_rel, b_rel, W_root, W_proj);
    scatter_kernel<<<(N_EDGES / 4 + 255) / 256, 256>>>(ei);
    final_kernel<<<(N_NODES / 2 + 255) / 256, 256>>>(b_proj, out);
}

// round 6
// speedup vs baseline: 1.1049x; 1.1049x over previous
#include <cuda_runtime.h>

#define N_NODES 100000
#define N_EDGES 1600000
#define HID 128
#define NBLK 148
#define NTHR 1024

typedef unsigned long long u64;

// Scratch (__device__ globals per allocation rules; zero-initialized)
__device__ float4 g_x4[N_NODES];    // (x0, x1, x2, 1.0)
__device__ float4 g_agg4[N_NODES];  // (sum x0, sum x1, sum x2, deg)
__device__ float4 g_w1[HID];        // (B0,B1,B2,C): B = W_lift@W_rel, C = b_lift@W_rel
__device__ float4 g_w2[HID];        // (A0,A1,A2,D): A = W_lift@W_root, D = b_lift@W_root + b_rel
__device__ float  g_wp[HID];        // W_proj
__device__ unsigned g_cnt[2];       // barrier arrival counters (self-resetting)
__device__ unsigned g_gen[2];       // barrier generations (monotonic)

__device__ __forceinline__ u64 pk(float lo, float hi) {
    u64 r; asm("mov.b64 %0, {%1, %2};" : "=l"(r) : "f"(lo), "f"(hi)); return r;
}
__device__ __forceinline__ u64 pk1(float v) { return pk(v, v); }
#define FMA2(d, a, b, c) asm("fma.rn.f32x2 %0, %1, %2, %3;" : "=l"(d) : "l"(a), "l"(b), "l"(c))
#define UNPK(lo, hi, v)  asm("mov.b64 {%0, %1}, %2;" : "=f"(lo), "=f"(hi) : "l"(v))

// Software grid barrier. Counter resets to 0 each use (deterministic across
// calls); generation grows monotonically (equality-compared, wrap-safe).
__device__ __forceinline__ void grid_barrier(int which) {
    __syncthreads();
    if (threadIdx.x == 0) {
        volatile unsigned* genp = (volatile unsigned*)&g_gen[which];
        unsigned gen = *genp;
        __threadfence();  // make this block's prior writes visible
        unsigned t = atomicAdd(&g_cnt[which], 1u);
        if (t == (unsigned)(NBLK - 1)) {
            g_cnt[which] = 0;
            __threadfence();
            *genp = gen + 1u;
        } else {
            while (*genp == gen) { }
        }
        __threadfence();  // acquire
    }
    __syncthreads();
}

__global__ void __launch_bounds__(NTHR, 1)
fused_kernel(const float* __restrict__ x,
             const int* __restrict__ ei,
             const float* __restrict__ W_lift,
             const float* __restrict__ b_lift,
             const float* __restrict__ W_rel,
             const float* __restrict__ b_rel,
             const float* __restrict__ W_root,
             const float* __restrict__ W_proj,
             const float* __restrict__ b_proj,
             float* __restrict__ out) {
    __shared__ float s_red[8][8][HID];  // prep reduce scratch (block 0 only)
    __shared__ u64 sB0[64], sB1[64], sB2[64], sC[64];
    __shared__ u64 sA0[64], sA1[64], sA2[64], sD[64], sWP[64];

    int tid = threadIdx.x;
    int bid = blockIdx.x;

    // ---------------- Phase 1: prep (block 0) / pack (blocks 1..147) --------
    if (bid == 0) {
        int f = tid & 127;
        int g = tid >> 7;  // 0..7, each sums 16 k's
        float b0 = 0.f, b1 = 0.f, b2 = 0.f, c = 0.f;
        float a0 = 0.f, a1 = 0.f, a2 = 0.f, d = 0.f;
        int k0 = g * 16;
#pragma unroll
        for (int i = 0; i < 16; i++) {
            int k = k0 + i;
            float wr = W_rel[k * HID + f];
            float wo = W_root[k * HID + f];
            float l0 = W_lift[0 * HID + k];
            float l1 = W_lift[1 * HID + k];
            float l2 = W_lift[2 * HID + k];
            float bl = b_lift[k];
            b0 += l0 * wr; b1 += l1 * wr; b2 += l2 * wr; c += bl * wr;
            a0 += l0 * wo; a1 += l1 * wo; a2 += l2 * wo; d += bl * wo;
        }
        s_red[g][0][f] = b0; s_red[g][1][f] = b1; s_red[g][2][f] = b2; s_red[g][3][f] = c;
        s_red[g][4][f] = a0; s_red[g][5][f] = a1; s_red[g][6][f] = a2; s_red[g][7][f] = d;
        __syncthreads();
        if (g == 0) {
            float s[8];
#pragma unroll
            for (int ch = 0; ch < 8; ch++) {
                float v = s_red[0][ch][f];
#pragma unroll
                for (int gg = 1; gg < 8; gg++) v += s_red[gg][ch][f];
                s[ch] = v;
            }
            g_w1[f] = make_float4(s[0], s[1], s[2], s[3]);
            g_w2[f] = make_float4(s[4], s[5], s[6], s[7] + b_rel[f]);
            g_wp[f] = W_proj[f];
        }
    } else {
        int n = (bid - 1) * NTHR + tid;  // 147*1024 = 150528 >= N_NODES
        if (n < N_NODES) {
            g_x4[n] = make_float4(x[3 * n], x[3 * n + 1], x[3 * n + 2], 1.0f);
            g_agg4[n] = make_float4(0.f, 0.f, 0.f, 0.f);
        }
    }

    grid_barrier(0);

    // Stage folded-weight tables into smem (hide under scatter; used in phase 3)
    if (tid < 64) {
        int p = tid;
        float4 u0 = g_w1[2 * p], u1 = g_w1[2 * p + 1];
        sB0[p] = pk(u0.x, u1.x); sB1[p] = pk(u0.y, u1.y);
        sB2[p] = pk(u0.z, u1.z); sC[p]  = pk(u0.w, u1.w);
        float4 v0 = g_w2[2 * p], v1 = g_w2[2 * p + 1];
        sA0[p] = pk(v0.x, v1.x); sA1[p] = pk(v0.y, v1.y);
        sA2[p] = pk(v0.z, v1.z); sD[p]  = pk(v0.w, v1.w);
        sWP[p] = pk(g_wp[2 * p], g_wp[2 * p + 1]);
    }

    // ---------------- Phase 2: scatter-add, 2 edges per thread iteration ----
    const int NPAIR = N_EDGES / 2;  // 800000
    for (int p = bid * NTHR + tid; p < NPAIR; p += NBLK * NTHR) {
        int2 s2 = *(const int2*)(ei + 2 * p);
        int2 d2 = *(const int2*)(ei + N_EDGES + 2 * p);
        float4 v0 = g_x4[(unsigned)s2.x];  // both gathers in flight
        float4 v1 = g_x4[(unsigned)s2.y];
        float* a0 = (float*)&g_agg4[(unsigned)d2.x];
        float* a1 = (float*)&g_agg4[(unsigned)d2.y];
        asm volatile("red.global.add.v4.f32 [%0], {%1,%2,%3,%4};"
                     :: "l"(a0), "f"(v0.x), "f"(v0.y), "f"(v0.z), "f"(v0.w) : "memory");
        asm volatile("red.global.add.v4.f32 [%0], {%1,%2,%3,%4};"
                     :: "l"(a1), "f"(v1.x), "f"(v1.y), "f"(v1.z), "f"(v1.w) : "memory");
    }

    grid_barrier(1);

    // ---------------- Phase 3: final, f32x2 math, 2 nodes per thread --------
    int pidx = bid * NTHR + tid;
    if (pidx < N_NODES / 2) {
        int n0 = pidx * 2;
        float4 aA = g_agg4[n0], aB = g_agg4[n0 + 1];
        float4 xA = g_x4[n0],  xB = g_x4[n0 + 1];

        u64 axA = pk1(aA.x), ayA = pk1(aA.y), azA = pk1(aA.z), awA = pk1(aA.w);
        u64 xxA = pk1(xA.x), xyA = pk1(xA.y), xzA = pk1(xA.z);
        u64 axB = pk1(aB.x), ayB = pk1(aB.y), azB = pk1(aB.z), awB = pk1(aB.w);
        u64 xxB = pk1(xB.x), xyB = pk1(xB.y), xzB = pk1(xB.z);

        u64 accA = pk(0.f, 0.f), accB = pk(0.f, 0.f);

#pragma unroll 8
        for (int p = 0; p < 64; p++) {
            u64 B0 = sB0[p], B1 = sB1[p], B2 = sB2[p], C = sC[p];
            u64 A0 = sA0[p], A1 = sA1[p], A2 = sA2[p], D = sD[p];
            u64 WP = sWP[p];

            u64 pA = D, pB = D;
            FMA2(pA, axA, B0, pA); FMA2(pB, axB, B0, pB);
            FMA2(pA, ayA, B1, pA); FMA2(pB, ayB, B1, pB);
            FMA2(pA, azA, B2, pA); FMA2(pB, azB, B2, pB);
            FMA2(pA, awA, C,  pA); FMA2(pB, awB, C,  pB);
            FMA2(pA, xxA, A0, pA); FMA2(pB, xxB, A0, pB);
            FMA2(pA, xyA, A1, pA); FMA2(pB, xyB, A1, pB);
            FMA2(pA, xzA, A2, pA); FMA2(pB, xzB, A2, pB);

            float a0, a1, b0, b1;
            UNPK(a0, a1, pA); UNPK(b0, b1, pB);
            float t0, t1, t2, t3;
            asm("tanh.approx.f32 %0, %1;" : "=f"(t0) : "f"(a0));
            asm("tanh.approx.f32 %0, %1;" : "=f"(t1) : "f"(a1));
            asm("tanh.approx.f32 %0, %1;" : "=f"(t2) : "f"(b0));
            asm("tanh.approx.f32 %0, %1;" : "=f"(t3) : "f"(b1));
            u64 tA = pk(t0, t1), tB = pk(t2, t3);
            FMA2(accA, tA, WP, accA);
            FMA2(accB, tB, WP, accB);
        }

        float rA0, rA1, rB0, rB1;
        UNPK(rA0, rA1, accA); UNPK(rB0, rB1, accB);
        float bp = b_proj[0];
        out[n0]     = rA0 + rA1 + bp;
        out[n0 + 1] = rB0 + rB1 + bp;
    }
}

// ---------------------------------------------------------------------------
// Launch — inputs: 0:x 1:edge_index(int32) 2:W_lift 3:b_lift 4:W_rel 5:b_rel
//                  6:W_root 7:W_proj 8:b_proj
// ---------------------------------------------------------------------------
extern "C" void kernel_launch(void* const* d_in, const int* in_sizes, int n_in,
                              void* d_out, int out_size) {
    const float* x      = (const float*)d_in[0];
    const int*   ei     = (const int*)d_in[1];
    const float* W_lift = (const float*)d_in[2];
    const float* b_lift = (const float*)d_in[3];
    const float* W_rel  = (const float*)d_in[4];
    const float* b_rel  = (const float*)d_in[5];
    const float* W_root = (const float*)d_in[6];
    const float* W_proj = (const float*)d_in[7];
    const float* b_proj = (const float*)d_in[8];
    float* out = (float*)d_out;

    fused_kernel<<<NBLK, NTHR>>>(x, ei, W_lift, b_lift, W_rel, b_rel,
                                 W_root, W_proj, b_proj, out);
}

// round 7
// speedup vs baseline: 1.1767x; 1.0649x over previous
#include <cuda_runtime.h>

#define N_NODES 100000
#define N_EDGES 1600000
#define HID 128

typedef unsigned long long u64;

// Scratch (__device__ globals per allocation rules)
__device__ float4 g_x4[N_NODES];    // (x0, x1, x2, 1.0)
__device__ float4 g_agg4[N_NODES];  // (sum x0, sum x1, sum x2, deg)

__device__ __forceinline__ u64 pk(float lo, float hi) {
    u64 r; asm("mov.b64 %0, {%1, %2};" : "=l"(r) : "f"(lo), "f"(hi)); return r;
}
__device__ __forceinline__ u64 pk1(float v) { return pk(v, v); }
#define FMA2(d, a, b, c) asm("fma.rn.f32x2 %0, %1, %2, %3;" : "=l"(d) : "l"(a), "l"(b), "l"(c))
#define UNPK(lo, hi, v)  asm("mov.b64 {%0, %1}, %2;" : "=f"(lo), "=f"(hi) : "l"(v))

// ---------------------------------------------------------------------------
// Kernel 1: pack x into (x0,x1,x2,1) float4 + zero agg
// ---------------------------------------------------------------------------
__global__ void pack_kernel(const float* __restrict__ x) {
    int n = blockIdx.x * blockDim.x + threadIdx.x;
    if (n >= N_NODES) return;
    g_x4[n] = make_float4(x[3 * n], x[3 * n + 1], x[3 * n + 2], 1.0f);
    g_agg4[n] = make_float4(0.f, 0.f, 0.f, 0.f);
}

// ---------------------------------------------------------------------------
// Kernel 2: scatter-add of (x,1) — 2 edges per thread, int2 index loads
// (R4's measured-best configuration; indices guaranteed in [0, N_NODES))
// ---------------------------------------------------------------------------
__global__ void scatter_kernel(const int* __restrict__ ei) {
    int t = blockIdx.x * blockDim.x + threadIdx.x;
    int e0 = t * 2;
    if (e0 >= N_EDGES) return;
    int2 s2 = *(const int2*)(ei + e0);
    int2 d2 = *(const int2*)(ei + N_EDGES + e0);

    float4 v0 = g_x4[(unsigned)s2.x];   // both gathers in flight
    float4 v1 = g_x4[(unsigned)s2.y];
    float* a0 = (float*)&g_agg4[(unsigned)d2.x];
    float* a1 = (float*)&g_agg4[(unsigned)d2.y];
    asm volatile("red.global.add.v4.f32 [%0], {%1,%2,%3,%4};"
                 :: "l"(a0), "f"(v0.x), "f"(v0.y), "f"(v0.z), "f"(v0.w) : "memory");
    asm volatile("red.global.add.v4.f32 [%0], {%1,%2,%3,%4};"
                 :: "l"(a1), "f"(v1.x), "f"(v1.y), "f"(v1.z), "f"(v1.w) : "memory");
}

// ---------------------------------------------------------------------------
// Kernel 3: fold weights (per-block prologue) + per-node output
//   fold: B = W_lift@W_rel, C = b_lift@W_rel, A = W_lift@W_root,
//         D = b_lift@W_root + b_rel
//   out[n] = sum_f tanh(dot(agg4,(B,C)_f) + dot(x4,(A,D)_f)) * wp_f + b_proj
// 256 threads, 2 nodes/thread, f32x2 packed math.
// ---------------------------------------------------------------------------
__global__ void __launch_bounds__(256)
final_kernel(const float* __restrict__ W_lift,
             const float* __restrict__ b_lift,
             const float* __restrict__ W_rel,
             const float* __restrict__ b_rel,
             const float* __restrict__ W_root,
             const float* __restrict__ W_proj,
             const float* __restrict__ b_proj,
             float* __restrict__ out) {
    __shared__ float red[2][8][HID];  // [kgroup][chain][f] = 8KB
    __shared__ u64 sB0[64], sB1[64], sB2[64], sC[64];
    __shared__ u64 sA0[64], sA1[64], sA2[64], sD[64], sWP[64];

    int tid = threadIdx.x;

    // Issue node loads first (hide under the fold computation)
    int pidx = blockIdx.x * 256 + tid;
    bool valid = pidx < N_NODES / 2;
    int n0 = pidx * 2;
    float4 aA, aB, xA, xB;
    if (valid) {
        aA = g_agg4[n0]; aB = g_agg4[n0 + 1];
        xA = g_x4[n0];   xB = g_x4[n0 + 1];
    }

    // ---- fold prologue: k split 2 ways (64 serial k each), f = tid&127 ----
    {
        int f = tid & 127;
        int g = tid >> 7;  // 0 or 1
        float b0 = 0.f, b1 = 0.f, b2 = 0.f, c = 0.f;
        float a0 = 0.f, a1 = 0.f, a2 = 0.f, d = 0.f;
        int k0 = g * 64;
#pragma unroll 16
        for (int i = 0; i < 64; i++) {
            int k = k0 + i;
            float wr = W_rel[k * HID + f];
            float wo = W_root[k * HID + f];
            float l0 = W_lift[0 * HID + k];
            float l1 = W_lift[1 * HID + k];
            float l2 = W_lift[2 * HID + k];
            float bl = b_lift[k];
            b0 += l0 * wr; b1 += l1 * wr; b2 += l2 * wr; c += bl * wr;
            a0 += l0 * wo; a1 += l1 * wo; a2 += l2 * wo; d += bl * wo;
        }
        red[g][0][f] = b0; red[g][1][f] = b1; red[g][2][f] = b2; red[g][3][f] = c;
        red[g][4][f] = a0; red[g][5][f] = a1; red[g][6][f] = a2; red[g][7][f] = d;
    }
    __syncthreads();
    if (tid < 64) {
        int p = tid;
        int fL = 2 * p, fH = 2 * p + 1;
        float s[8][2];
#pragma unroll
        for (int ch = 0; ch < 8; ch++) {
            s[ch][0] = red[0][ch][fL] + red[1][ch][fL];
            s[ch][1] = red[0][ch][fH] + red[1][ch][fH];
        }
        sB0[p] = pk(s[0][0], s[0][1]);
        sB1[p] = pk(s[1][0], s[1][1]);
        sB2[p] = pk(s[2][0], s[2][1]);
        sC[p]  = pk(s[3][0], s[3][1]);
        sA0[p] = pk(s[4][0], s[4][1]);
        sA1[p] = pk(s[5][0], s[5][1]);
        sA2[p] = pk(s[6][0], s[6][1]);
        sD[p]  = pk(s[7][0] + b_rel[fL], s[7][1] + b_rel[fH]);
        sWP[p] = pk(W_proj[fL], W_proj[fH]);
    }
    __syncthreads();

    if (!valid) return;

    u64 axA = pk1(aA.x), ayA = pk1(aA.y), azA = pk1(aA.z), awA = pk1(aA.w);
    u64 xxA = pk1(xA.x), xyA = pk1(xA.y), xzA = pk1(xA.z);
    u64 axB = pk1(aB.x), ayB = pk1(aB.y), azB = pk1(aB.z), awB = pk1(aB.w);
    u64 xxB = pk1(xB.x), xyB = pk1(xB.y), xzB = pk1(xB.z);

    u64 accA = pk(0.f, 0.f), accB = pk(0.f, 0.f);

#pragma unroll 8
    for (int p = 0; p < 64; p++) {
        u64 B0 = sB0[p], B1 = sB1[p], B2 = sB2[p], C = sC[p];
        u64 A0 = sA0[p], A1 = sA1[p], A2 = sA2[p], D = sD[p];
        u64 WP = sWP[p];

        u64 pA = D, pB = D;
        FMA2(pA, axA, B0, pA); FMA2(pB, axB, B0, pB);
        FMA2(pA, ayA, B1, pA); FMA2(pB, ayB, B1, pB);
        FMA2(pA, azA, B2, pA); FMA2(pB, azB, B2, pB);
        FMA2(pA, awA, C,  pA); FMA2(pB, awB, C,  pB);
        FMA2(pA, xxA, A0, pA); FMA2(pB, xxB, A0, pB);
        FMA2(pA, xyA, A1, pA); FMA2(pB, xyB, A1, pB);
        FMA2(pA, xzA, A2, pA); FMA2(pB, xzB, A2, pB);

        float a0, a1, b0, b1;
        UNPK(a0, a1, pA); UNPK(b0, b1, pB);
        float t0, t1, t2, t3;
        asm("tanh.approx.f32 %0, %1;" : "=f"(t0) : "f"(a0));
        asm("tanh.approx.f32 %0, %1;" : "=f"(t1) : "f"(a1));
        asm("tanh.approx.f32 %0, %1;" : "=f"(t2) : "f"(b0));
        asm("tanh.approx.f32 %0, %1;" : "=f"(t3) : "f"(b1));
        u64 tA = pk(t0, t1), tB = pk(t2, t3);
        FMA2(accA, tA, WP, accA);
        FMA2(accB, tB, WP, accB);
    }

    float rA0, rA1, rB0, rB1;
    UNPK(rA0, rA1, accA); UNPK(rB0, rB1, accB);
    float bp = b_proj[0];
    out[n0]     = rA0 + rA1 + bp;
    out[n0 + 1] = rB0 + rB1 + bp;
}

// ---------------------------------------------------------------------------
// Launch — inputs: 0:x 1:edge_index(int32) 2:W_lift 3:b_lift 4:W_rel 5:b_rel
//                  6:W_root 7:W_proj 8:b_proj
// ---------------------------------------------------------------------------
extern "C" void kernel_launch(void* const* d_in, const int* in_sizes, int n_in,
                              void* d_out, int out_size) {
    const float* x      = (const float*)d_in[0];
    const int*   ei     = (const int*)d_in[1];
    const float* W_lift = (const float*)d_in[2];
    const float* b_lift = (const float*)d_in[3];
    const float* W_rel  = (const float*)d_in[4];
    const float* b_rel  = (const float*)d_in[5];
    const float* W_root = (const float*)d_in[6];
    const float* W_proj = (const float*)d_in[7];
    const float* b_proj = (const float*)d_in[8];
    float* out = (float*)d_out;

    pack_kernel<<<(N_NODES + 255) / 256, 256>>>(x);
    scatter_kernel<<<(N_EDGES / 2 + 255) / 256, 256>>>(ei);
    final_kernel<<<(N_NODES / 2 + 255) / 256, 256>>>(
        W_lift, b_lift, W_rel, b_rel, W_root, W_proj, b_proj, out);
}

// round 8
// speedup vs baseline: 1.2971x; 1.1024x over previous
#include <cuda_runtime.h>

#define N_NODES 100000
#define N_EDGES 1600000
#define HID 128

typedef unsigned long long u64;

// Scratch (__device__ globals per allocation rules)
__device__ float4 g_x4[N_NODES];    // (x0, x1, x2, 1.0)
__device__ float4 g_agg4[N_NODES];  // (sum x0, sum x1, sum x2, deg)
__device__ float4 g_w1[HID];        // (B0,B1,B2,C): B = W_lift@W_rel, C = b_lift@W_rel
__device__ float4 g_w2[HID];        // (A0,A1,A2,D): A = W_lift@W_root, D = b_lift@W_root + b_rel
__device__ float  g_wp[HID];        // W_proj

__device__ __forceinline__ u64 pk(float lo, float hi) {
    u64 r; asm("mov.b64 %0, {%1, %2};" : "=l"(r) : "f"(lo), "f"(hi)); return r;
}
__device__ __forceinline__ u64 pk1(float v) { return pk(v, v); }
#define FMA2(d, a, b, c) asm("fma.rn.f32x2 %0, %1, %2, %3;" : "=l"(d) : "l"(a), "l"(b), "l"(c))
#define UNPK(lo, hi, v)  asm("mov.b64 {%0, %1}, %2;" : "=f"(lo), "=f"(hi) : "l"(v))

// ---------------------------------------------------------------------------
// Kernel 1: pack x into (x0,x1,x2,1) float4 + zero agg
// ---------------------------------------------------------------------------
__global__ void pack_kernel(const float* __restrict__ x) {
    int n = blockIdx.x * blockDim.x + threadIdx.x;
    if (n >= N_NODES) return;
    g_x4[n] = make_float4(x[3 * n], x[3 * n + 1], x[3 * n + 2], 1.0f);
    g_agg4[n] = make_float4(0.f, 0.f, 0.f, 0.f);
}

// ---------------------------------------------------------------------------
// Kernel 2: block 0 = weight fold (hidden under scatter);
//           blocks 1.. = scatter-add of (x,1), 4 edges/thread, int4 indices
// ---------------------------------------------------------------------------
__global__ void __launch_bounds__(256)
scatter_kernel(const int* __restrict__ ei,
               const float* __restrict__ W_lift,
               const float* __restrict__ b_lift,
               const float* __restrict__ W_rel,
               const float* __restrict__ b_rel,
               const float* __restrict__ W_root,
               const float* __restrict__ W_proj) {
    if (blockIdx.x == 0) {
        // ---- weight fold: f = tid&127, k split 2 ways ----
        __shared__ float red[2][8][HID];  // 8KB
        int f = threadIdx.x & 127;
        int g = threadIdx.x >> 7;  // 0 or 1
        float b0 = 0.f, b1 = 0.f, b2 = 0.f, c = 0.f;
        float a0 = 0.f, a1 = 0.f, a2 = 0.f, d = 0.f;
        int k0 = g * 64;
#pragma unroll 16
        for (int i = 0; i < 64; i++) {
            int k = k0 + i;
            float wr = W_rel[k * HID + f];
            float wo = W_root[k * HID + f];
            float l0 = W_lift[0 * HID + k];
            float l1 = W_lift[1 * HID + k];
            float l2 = W_lift[2 * HID + k];
            float bl = b_lift[k];
            b0 += l0 * wr; b1 += l1 * wr; b2 += l2 * wr; c += bl * wr;
            a0 += l0 * wo; a1 += l1 * wo; a2 += l2 * wo; d += bl * wo;
        }
        red[g][0][f] = b0; red[g][1][f] = b1; red[g][2][f] = b2; red[g][3][f] = c;
        red[g][4][f] = a0; red[g][5][f] = a1; red[g][6][f] = a2; red[g][7][f] = d;
        __syncthreads();
        if (g == 0) {
            float s[8];
#pragma unroll
            for (int ch = 0; ch < 8; ch++) s[ch] = red[0][ch][f] + red[1][ch][f];
            g_w1[f] = make_float4(s[0], s[1], s[2], s[3]);
            g_w2[f] = make_float4(s[4], s[5], s[6], s[7] + b_rel[f]);
            g_wp[f] = W_proj[f];
        }
        return;
    }

    // ---- scatter: 4 edges per thread ----
    int t = (blockIdx.x - 1) * 256 + threadIdx.x;
    int e0 = t * 4;
    if (e0 >= N_EDGES) return;
    int4 s4 = *(const int4*)(ei + e0);            // 4 src indices (16B)
    int4 d4 = *(const int4*)(ei + N_EDGES + e0);  // 4 dst indices (16B)

    // all 4 gathers in flight before any red
    float4 v0 = __ldg(&g_x4[(unsigned)s4.x]);
    float4 v1 = __ldg(&g_x4[(unsigned)s4.y]);
    float4 v2 = __ldg(&g_x4[(unsigned)s4.z]);
    float4 v3 = __ldg(&g_x4[(unsigned)s4.w]);

    float* a0 = (float*)&g_agg4[(unsigned)d4.x];
    float* a1 = (float*)&g_agg4[(unsigned)d4.y];
    float* a2 = (float*)&g_agg4[(unsigned)d4.z];
    float* a3 = (float*)&g_agg4[(unsigned)d4.w];
    asm volatile("red.global.add.v4.f32 [%0], {%1,%2,%3,%4};"
                 :: "l"(a0), "f"(v0.x), "f"(v0.y), "f"(v0.z), "f"(v0.w) : "memory");
    asm volatile("red.global.add.v4.f32 [%0], {%1,%2,%3,%4};"
                 :: "l"(a1), "f"(v1.x), "f"(v1.y), "f"(v1.z), "f"(v1.w) : "memory");
    asm volatile("red.global.add.v4.f32 [%0], {%1,%2,%3,%4};"
                 :: "l"(a2), "f"(v2.x), "f"(v2.y), "f"(v2.z), "f"(v2.w) : "memory");
    asm volatile("red.global.add.v4.f32 [%0], {%1,%2,%3,%4};"
                 :: "l"(a3), "f"(v3.x), "f"(v3.y), "f"(v3.z), "f"(v3.w) : "memory");
}

// ---------------------------------------------------------------------------
// Kernel 3: out[n] = sum_f tanh(dot(agg4,w1_f)+dot(x4,w2_f)) * wp_f + b_proj
// f32x2 packed math; 2 nodes per thread; tables from g_w (folded in kernel 2)
// ---------------------------------------------------------------------------
__global__ void __launch_bounds__(256)
final_kernel(const float* __restrict__ b_proj, float* __restrict__ out) {
    __shared__ u64 sB0[64], sB1[64], sB2[64], sC[64];
    __shared__ u64 sA0[64], sA1[64], sA2[64], sD[64], sWP[64];
    if (threadIdx.x < 64) {
        int p = threadIdx.x;
        float4 u0 = g_w1[2 * p], u1 = g_w1[2 * p + 1];
        sB0[p] = pk(u0.x, u1.x); sB1[p] = pk(u0.y, u1.y);
        sB2[p] = pk(u0.z, u1.z); sC[p]  = pk(u0.w, u1.w);
        float4 v0 = g_w2[2 * p], v1 = g_w2[2 * p + 1];
        sA0[p] = pk(v0.x, v1.x); sA1[p] = pk(v0.y, v1.y);
        sA2[p] = pk(v0.z, v1.z); sD[p]  = pk(v0.w, v1.w);
        sWP[p] = pk(g_wp[2 * p], g_wp[2 * p + 1]);
    }
    __syncthreads();

    int pidx = blockIdx.x * blockDim.x + threadIdx.x;
    if (pidx >= N_NODES / 2) return;
    int n0 = pidx * 2;

    float4 aA = g_agg4[n0], aB = g_agg4[n0 + 1];
    float4 xA = g_x4[n0],  xB = g_x4[n0 + 1];

    u64 axA = pk1(aA.x), ayA = pk1(aA.y), azA = pk1(aA.z), awA = pk1(aA.w);
    u64 xxA = pk1(xA.x), xyA = pk1(xA.y), xzA = pk1(xA.z);
    u64 axB = pk1(aB.x), ayB = pk1(aB.y), azB = pk1(aB.z), awB = pk1(aB.w);
    u64 xxB = pk1(xB.x), xyB = pk1(xB.y), xzB = pk1(xB.z);

    u64 accA = pk(0.f, 0.f), accB = pk(0.f, 0.f);

#pragma unroll 8
    for (int p = 0; p < 64; p++) {
        u64 B0 = sB0[p], B1 = sB1[p], B2 = sB2[p], C = sC[p];
        u64 A0 = sA0[p], A1 = sA1[p], A2 = sA2[p], D = sD[p];
        u64 WP = sWP[p];

        u64 pA = D, pB = D;
        FMA2(pA, axA, B0, pA); FMA2(pB, axB, B0, pB);
        FMA2(pA, ayA, B1, pA); FMA2(pB, ayB, B1, pB);
        FMA2(pA, azA, B2, pA); FMA2(pB, azB, B2, pB);
        FMA2(pA, awA, C,  pA); FMA2(pB, awB, C,  pB);
        FMA2(pA, xxA, A0, pA); FMA2(pB, xxB, A0, pB);
        FMA2(pA, xyA, A1, pA); FMA2(pB, xyB, A1, pB);
        FMA2(pA, xzA, A2, pA); FMA2(pB, xzB, A2, pB);

        float a0, a1, b0, b1;
        UNPK(a0, a1, pA); UNPK(b0, b1, pB);
        float t0, t1, t2, t3;
        asm("tanh.approx.f32 %0, %1;" : "=f"(t0) : "f"(a0));
        asm("tanh.approx.f32 %0, %1;" : "=f"(t1) : "f"(a1));
        asm("tanh.approx.f32 %0, %1;" : "=f"(t2) : "f"(b0));
        asm("tanh.approx.f32 %0, %1;" : "=f"(t3) : "f"(b1));
        u64 tA = pk(t0, t1), tB = pk(t2, t3);
        FMA2(accA, tA, WP, accA);
        FMA2(accB, tB, WP, accB);
    }

    float rA0, rA1, rB0, rB1;
    UNPK(rA0, rA1, accA); UNPK(rB0, rB1, accB);
    float bp = b_proj[0];
    out[n0]     = rA0 + rA1 + bp;
    out[n0 + 1] = rB0 + rB1 + bp;
}

// ---------------------------------------------------------------------------
// Launch — inputs: 0:x 1:edge_index(int32) 2:W_lift 3:b_lift 4:W_rel 5:b_rel
//                  6:W_root 7:W_proj 8:b_proj
// ---------------------------------------------------------------------------
extern "C" void kernel_launch(void* const* d_in, const int* in_sizes, int n_in,
                              void* d_out, int out_size) {
    const float* x      = (const float*)d_in[0];
    const int*   ei     = (const int*)d_in[1];
    const float* W_lift = (const float*)d_in[2];
    const float* b_lift = (const float*)d_in[3];
    const float* W_rel  = (const float*)d_in[4];
    const float* b_rel  = (const float*)d_in[5];
    const float* W_root = (const float*)d_in[6];
    const float* W_proj = (const float*)d_in[7];
    const float* b_proj = (const float*)d_in[8];
    float* out = (float*)d_out;

    pack_kernel<<<(N_NODES + 255) / 256, 256>>>(x);
    scatter_kernel<<<1 + (N_EDGES / 4 + 255) / 256, 256>>>(
        ei, W_lift, b_lift, W_rel, b_rel, W_root, W_proj);
    final_kernel<<<(N_NODES / 2 + 255) / 256, 256>>>(b_proj, out);
}